// round 1
// baseline (speedup 1.0000x reference)
#include <cuda_runtime.h>

// CPQuadRankLayer: B=64, N=1024, C=4, R=64, D=O=128
//  projected[b,n,c,r] = sum_i x[b,n,c,i] * factors[c,n,r,i]
//  p = projected / rms_over_r(projected)
//  merged[b,n,r] = prod_c p[...,c,r] * gain[n]
//  out[b,n,o] = sum_r merged * factor_out[n,r,o] + mean_c x[b,n,c,o]

#define B_   64
#define N_   1024
#define C_   4
#define R_   64
#define D_   128
#define O_   128

constexpr int PAD    = 68;   // floats per smem row (16B-aligned vec4, decorrelates banks)
constexpr int CHUNK  = 32;   // i-chunk size

// dynamic smem layout (floats):
//  [0 .. 8704)        xs[c][il][b]   : 4*32*68   (phase A)
//  [8704 .. 17408)    fs[c][il][r]   : 4*32*68   (phase A)
//  [0 .. 17408)       p_s[c][b][r]   : 4*64*68   (phase B, overlays A)
//  [0 .. 2048)        fo_s[16][128]             (phase C, overlays B)
//  [17408 .. 21760)   merged_s[b][r] : 64*68
constexpr int XS_OFF     = 0;
constexpr int FS_OFF     = 4 * CHUNK * PAD;          // 8704
constexpr int MERGED_OFF = 2 * 4 * CHUNK * PAD;      // 17408
constexpr int SMEM_FLOATS = MERGED_OFF + 64 * PAD;   // 21760
constexpr int SMEM_BYTES  = SMEM_FLOATS * 4;         // 87040

__global__ __launch_bounds__(256, 1)
void cpquad_kernel(const float* __restrict__ x,
                   const float* __restrict__ factors,
                   const float* __restrict__ fo,
                   const float* __restrict__ gain,
                   float* __restrict__ out)
{
    extern __shared__ float sm[];
    const int n = blockIdx.x;
    const int t = threadIdx.x;

    // phase A mapping: c = t[7:6], btile = t[5:3], rtile = t[2:0]
    const int c     = t >> 6;
    const int btile = (t >> 3) & 7;
    const int rtile = t & 7;

    const float g = __ldg(&gain[n]);

    float acc[8][8];
#pragma unroll
    for (int j = 0; j < 8; j++)
#pragma unroll
        for (int k = 0; k < 8; k++) acc[j][k] = 0.0f;

    // ---------------- Phase A: projected = x @ factors^T (per c) ----------------
    for (int ic = 0; ic < 4; ic++) {
        // cooperative load of chunk: 2048 float4 per array, 8 per thread.
        // q decomposition: qc = c, row = b (or r), i4 = float4-in-chunk
#pragma unroll
        for (int j = 0; j < 8; j++) {
            const int q   = j * 256 + t;
            const int qc  = q >> 9;
            const int rem = q & 511;
            const int row = rem >> 3;
            const int i4  = rem & 7;
            const int i   = ic * CHUNK + i4 * 4;
            const int il  = i4 * 4;

            const float4 xv = *(const float4*)&x[((row * N_ + n) * C_ + qc) * D_ + i];
            sm[XS_OFF + (qc * CHUNK + il + 0) * PAD + row] = xv.x;
            sm[XS_OFF + (qc * CHUNK + il + 1) * PAD + row] = xv.y;
            sm[XS_OFF + (qc * CHUNK + il + 2) * PAD + row] = xv.z;
            sm[XS_OFF + (qc * CHUNK + il + 3) * PAD + row] = xv.w;

            const float4 fv = *(const float4*)&factors[((qc * N_ + n) * R_ + row) * D_ + i];
            sm[FS_OFF + (qc * CHUNK + il + 0) * PAD + row] = fv.x;
            sm[FS_OFF + (qc * CHUNK + il + 1) * PAD + row] = fv.y;
            sm[FS_OFF + (qc * CHUNK + il + 2) * PAD + row] = fv.z;
            sm[FS_OFF + (qc * CHUNK + il + 3) * PAD + row] = fv.w;
        }
        __syncthreads();

        const float* xbase = &sm[XS_OFF + (c * CHUNK) * PAD + btile * 8];
        const float* fbase = &sm[FS_OFF + (c * CHUNK) * PAD + rtile * 8];
#pragma unroll
        for (int i = 0; i < CHUNK; i++) {
            const float4 xa = *(const float4*)&xbase[i * PAD];
            const float4 xb = *(const float4*)&xbase[i * PAD + 4];
            const float4 fa = *(const float4*)&fbase[i * PAD];
            const float4 fb = *(const float4*)&fbase[i * PAD + 4];
            float xr[8] = {xa.x, xa.y, xa.z, xa.w, xb.x, xb.y, xb.z, xb.w};
            float fr[8] = {fa.x, fa.y, fa.z, fa.w, fb.x, fb.y, fb.z, fb.w};
#pragma unroll
            for (int j = 0; j < 8; j++)
#pragma unroll
                for (int k = 0; k < 8; k++)
                    acc[j][k] = fmaf(xr[j], fr[k], acc[j][k]);
        }
        __syncthreads();
    }

    // ---------------- Phase B: RMSNorm over r, write p to smem ----------------
    // lanes sharing (c, btile) differ only in rtile = lane[2:0] -> shuffle over 8 lanes
#pragma unroll
    for (int j = 0; j < 8; j++) {
        float ss = 0.0f;
#pragma unroll
        for (int k = 0; k < 8; k++) ss = fmaf(acc[j][k], acc[j][k], ss);
        ss += __shfl_xor_sync(0xffffffffu, ss, 1);
        ss += __shfl_xor_sync(0xffffffffu, ss, 2);
        ss += __shfl_xor_sync(0xffffffffu, ss, 4);
        const float rinv = rsqrtf(ss * (1.0f / 64.0f) + 1e-6f);
        const int b = btile * 8 + j;
        float4 v0, v1;
        v0.x = acc[j][0] * rinv; v0.y = acc[j][1] * rinv;
        v0.z = acc[j][2] * rinv; v0.w = acc[j][3] * rinv;
        v1.x = acc[j][4] * rinv; v1.y = acc[j][5] * rinv;
        v1.z = acc[j][6] * rinv; v1.w = acc[j][7] * rinv;
        *(float4*)&sm[(c * 64 + b) * PAD + rtile * 8]     = v0;
        *(float4*)&sm[(c * 64 + b) * PAD + rtile * 8 + 4] = v1;
    }
    __syncthreads();

    // merged[b][r] = prod_c p * gain
#pragma unroll
    for (int j = 0; j < 4; j++) {
        const int q  = j * 256 + t;       // 1024 float4s
        const int b  = q >> 4;
        const int r4 = q & 15;
        const int off = b * PAD + r4 * 4;
        const float4 p0 = *(const float4*)&sm[(0 * 64) * PAD + off];
        const float4 p1 = *(const float4*)&sm[(1 * 64) * PAD + off];
        const float4 p2 = *(const float4*)&sm[(2 * 64) * PAD + off];
        const float4 p3 = *(const float4*)&sm[(3 * 64) * PAD + off];
        float4 m;
        m.x = p0.x * p1.x * p2.x * p3.x * g;
        m.y = p0.y * p1.y * p2.y * p3.y * g;
        m.z = p0.z * p1.z * p2.z * p3.z * g;
        m.w = p0.w * p1.w * p2.w * p3.w * g;
        *(float4*)&sm[MERGED_OFF + b * PAD + r4 * 4] = m;
    }
    __syncthreads();

    // ---------------- Phase C: out = merged @ factor_out + residual ----------------
    const int to = t & 31;   // o-tile (float4): o = to*4
    const int bq = t >> 5;   // b-octet: b = bq*8 + j   (warp = fixed bq -> merged reads broadcast)
    float acc2[8][4];
#pragma unroll
    for (int j = 0; j < 8; j++)
#pragma unroll
        for (int u = 0; u < 4; u++) acc2[j][u] = 0.0f;

    for (int rc = 0; rc < 4; rc++) {
        // stage fo[n, rc*16 .. +16, :] into sm[0..2048) (p_s fully consumed)
#pragma unroll
        for (int j2 = 0; j2 < 2; j2++) {
            const int q  = j2 * 256 + t;   // 512 float4
            const int rl = q >> 5;
            const int o4 = q & 31;
            const float4 v = *(const float4*)&fo[(n * R_ + rc * 16 + rl) * O_ + o4 * 4];
            *(float4*)&sm[rl * 128 + o4 * 4] = v;
        }
        __syncthreads();
#pragma unroll
        for (int rl = 0; rl < 16; rl++) {
            const int r = rc * 16 + rl;
            const float4 fv = *(const float4*)&sm[rl * 128 + to * 4];
#pragma unroll
            for (int j = 0; j < 8; j++) {
                const float m = sm[MERGED_OFF + (bq * 8 + j) * PAD + r];
                acc2[j][0] = fmaf(m, fv.x, acc2[j][0]);
                acc2[j][1] = fmaf(m, fv.y, acc2[j][1]);
                acc2[j][2] = fmaf(m, fv.z, acc2[j][2]);
                acc2[j][3] = fmaf(m, fv.w, acc2[j][3]);
            }
        }
        __syncthreads();
    }

    // residual (mean over c of x) + store
#pragma unroll
    for (int j = 0; j < 8; j++) {
        const int b = bq * 8 + j;
        const int xb = ((b * N_ + n) * C_) * D_ + to * 4;
        const float4 r0 = *(const float4*)&x[xb + 0 * D_];
        const float4 r1 = *(const float4*)&x[xb + 1 * D_];
        const float4 r2 = *(const float4*)&x[xb + 2 * D_];
        const float4 r3 = *(const float4*)&x[xb + 3 * D_];
        float4 o;
        o.x = acc2[j][0] + 0.25f * (r0.x + r1.x + r2.x + r3.x);
        o.y = acc2[j][1] + 0.25f * (r0.y + r1.y + r2.y + r3.y);
        o.z = acc2[j][2] + 0.25f * (r0.z + r1.z + r2.z + r3.z);
        o.w = acc2[j][3] + 0.25f * (r0.w + r1.w + r2.w + r3.w);
        *(float4*)&out[(b * N_ + n) * O_ + to * 4] = o;
    }
}

extern "C" void kernel_launch(void* const* d_in, const int* in_sizes, int n_in,
                              void* d_out, int out_size)
{
    const float* x       = (const float*)d_in[0];
    const float* factors = (const float*)d_in[1];
    const float* fo      = (const float*)d_in[2];
    const float* gain    = (const float*)d_in[3];
    float* out = (float*)d_out;

    cudaFuncSetAttribute(cpquad_kernel,
                         cudaFuncAttributeMaxDynamicSharedMemorySize, SMEM_BYTES);
    cpquad_kernel<<<N_, 256, SMEM_BYTES>>>(x, factors, fo, gain, out);
}

// round 2
// speedup vs baseline: 1.0106x; 1.0106x over previous
#include <cuda_runtime.h>

// CPQuadRankLayer: B=64, N=1024, C=4, R=64, D=O=128
//  projected[b,n,c,r] = sum_i x[b,n,c,i] * factors[c,n,r,i]
//  p = projected / rms_over_r(projected)
//  merged[b,n,r] = prod_c p[...,c,r] * gain[n]
//  out[b,n,o] = sum_r merged * factor_out[n,r,o] + mean_c x[b,n,c,o]

#define B_   64
#define N_   1024
#define C_   4
#define R_   64
#define D_   128
#define O_   128

constexpr int PAD    = 68;   // floats per smem row (16B-aligned vec4, decorrelates banks)
constexpr int CHUNK  = 32;   // i-chunk size

// dynamic smem layout (floats):
//  [0 .. 8704)        xs[c][il][b]   : 4*32*68   (phase A)
//  [8704 .. 17408)    fs[c][il][r]   : 4*32*68   (phase A)
//  [0 .. 17408)       p_s[c][b][r]   : 4*64*68   (phase B, overlays A)
//  [0 .. 2048)        fo_s[16][128]             (phase C, overlays B)
//  [17408 .. 21760)   merged_s[b][r] : 64*68
constexpr int XS_OFF     = 0;
constexpr int FS_OFF     = 4 * CHUNK * PAD;          // 8704
constexpr int MERGED_OFF = 2 * 4 * CHUNK * PAD;      // 17408
constexpr int SMEM_FLOATS = MERGED_OFF + 64 * PAD;   // 21760
constexpr int SMEM_BYTES  = SMEM_FLOATS * 4;         // 87040

__global__ __launch_bounds__(256, 1)
void cpquad_kernel(const float* __restrict__ x,
                   const float* __restrict__ factors,
                   const float* __restrict__ fo,
                   const float* __restrict__ gain,
                   float* __restrict__ out)
{
    extern __shared__ float sm[];
    const int n = blockIdx.x;
    const int t = threadIdx.x;

    // phase A mapping: c = t[7:6], btile = t[5:3], rtile = t[2:0]
    const int c     = t >> 6;
    const int btile = (t >> 3) & 7;
    const int rtile = t & 7;

    const float g = __ldg(&gain[n]);

    float acc[8][8];
#pragma unroll
    for (int j = 0; j < 8; j++)
#pragma unroll
        for (int k = 0; k < 8; k++) acc[j][k] = 0.0f;

    // ---------------- Phase A: projected = x @ factors^T (per c) ----------------
    for (int ic = 0; ic < 4; ic++) {
        // cooperative load of chunk: 2048 float4 per array, 8 per thread.
        // q decomposition: qc = c, row = b (or r), i4 = float4-in-chunk
#pragma unroll
        for (int j = 0; j < 8; j++) {
            const int q   = j * 256 + t;
            const int qc  = q >> 9;
            const int rem = q & 511;
            const int row = rem >> 3;
            const int i4  = rem & 7;
            const int i   = ic * CHUNK + i4 * 4;
            const int il  = i4 * 4;

            const float4 xv = *(const float4*)&x[((row * N_ + n) * C_ + qc) * D_ + i];
            sm[XS_OFF + (qc * CHUNK + il + 0) * PAD + row] = xv.x;
            sm[XS_OFF + (qc * CHUNK + il + 1) * PAD + row] = xv.y;
            sm[XS_OFF + (qc * CHUNK + il + 2) * PAD + row] = xv.z;
            sm[XS_OFF + (qc * CHUNK + il + 3) * PAD + row] = xv.w;

            const float4 fv = *(const float4*)&factors[((qc * N_ + n) * R_ + row) * D_ + i];
            sm[FS_OFF + (qc * CHUNK + il + 0) * PAD + row] = fv.x;
            sm[FS_OFF + (qc * CHUNK + il + 1) * PAD + row] = fv.y;
            sm[FS_OFF + (qc * CHUNK + il + 2) * PAD + row] = fv.z;
            sm[FS_OFF + (qc * CHUNK + il + 3) * PAD + row] = fv.w;
        }
        __syncthreads();

        const float* xbase = &sm[XS_OFF + (c * CHUNK) * PAD + btile * 8];
        const float* fbase = &sm[FS_OFF + (c * CHUNK) * PAD + rtile * 8];
#pragma unroll
        for (int i = 0; i < CHUNK; i++) {
            const float4 xa = *(const float4*)&xbase[i * PAD];
            const float4 xb = *(const float4*)&xbase[i * PAD + 4];
            const float4 fa = *(const float4*)&fbase[i * PAD];
            const float4 fb = *(const float4*)&fbase[i * PAD + 4];
            float xr[8] = {xa.x, xa.y, xa.z, xa.w, xb.x, xb.y, xb.z, xb.w};
            float fr[8] = {fa.x, fa.y, fa.z, fa.w, fb.x, fb.y, fb.z, fb.w};
#pragma unroll
            for (int j = 0; j < 8; j++)
#pragma unroll
                for (int k = 0; k < 8; k++)
                    acc[j][k] = fmaf(xr[j], fr[k], acc[j][k]);
        }
        __syncthreads();
    }

    // ---------------- Phase B: RMSNorm over r, write p to smem ----------------
    // lanes sharing (c, btile) differ only in rtile = lane[2:0] -> shuffle over 8 lanes
#pragma unroll
    for (int j = 0; j < 8; j++) {
        float ss = 0.0f;
#pragma unroll
        for (int k = 0; k < 8; k++) ss = fmaf(acc[j][k], acc[j][k], ss);
        ss += __shfl_xor_sync(0xffffffffu, ss, 1);
        ss += __shfl_xor_sync(0xffffffffu, ss, 2);
        ss += __shfl_xor_sync(0xffffffffu, ss, 4);
        const float rinv = rsqrtf(ss * (1.0f / 64.0f) + 1e-6f);
        const int b = btile * 8 + j;
        float4 v0, v1;
        v0.x = acc[j][0] * rinv; v0.y = acc[j][1] * rinv;
        v0.z = acc[j][2] * rinv; v0.w = acc[j][3] * rinv;
        v1.x = acc[j][4] * rinv; v1.y = acc[j][5] * rinv;
        v1.z = acc[j][6] * rinv; v1.w = acc[j][7] * rinv;
        *(float4*)&sm[(c * 64 + b) * PAD + rtile * 8]     = v0;
        *(float4*)&sm[(c * 64 + b) * PAD + rtile * 8 + 4] = v1;
    }
    __syncthreads();

    // merged[b][r] = prod_c p * gain
#pragma unroll
    for (int j = 0; j < 4; j++) {
        const int q  = j * 256 + t;       // 1024 float4s
        const int b  = q >> 4;
        const int r4 = q & 15;
        const int off = b * PAD + r4 * 4;
        const float4 p0 = *(const float4*)&sm[(0 * 64) * PAD + off];
        const float4 p1 = *(const float4*)&sm[(1 * 64) * PAD + off];
        const float4 p2 = *(const float4*)&sm[(2 * 64) * PAD + off];
        const float4 p3 = *(const float4*)&sm[(3 * 64) * PAD + off];
        float4 m;
        m.x = p0.x * p1.x * p2.x * p3.x * g;
        m.y = p0.y * p1.y * p2.y * p3.y * g;
        m.z = p0.z * p1.z * p2.z * p3.z * g;
        m.w = p0.w * p1.w * p2.w * p3.w * g;
        *(float4*)&sm[MERGED_OFF + b * PAD + r4 * 4] = m;
    }
    __syncthreads();

    // ---------------- Phase C: out = merged @ factor_out + residual ----------------
    const int to = t & 31;   // o-tile (float4): o = to*4
    const int bq = t >> 5;   // b-octet: b = bq*8 + j   (warp = fixed bq -> merged reads broadcast)
    float acc2[8][4];
#pragma unroll
    for (int j = 0; j < 8; j++)
#pragma unroll
        for (int u = 0; u < 4; u++) acc2[j][u] = 0.0f;

    for (int rc = 0; rc < 4; rc++) {
        // stage fo[n, rc*16 .. +16, :] into sm[0..2048) (p_s fully consumed)
#pragma unroll
        for (int j2 = 0; j2 < 2; j2++) {
            const int q  = j2 * 256 + t;   // 512 float4
            const int rl = q >> 5;
            const int o4 = q & 31;
            const float4 v = *(const float4*)&fo[(n * R_ + rc * 16 + rl) * O_ + o4 * 4];
            *(float4*)&sm[rl * 128 + o4 * 4] = v;
        }
        __syncthreads();
#pragma unroll
        for (int rl = 0; rl < 16; rl++) {
            const int r = rc * 16 + rl;
            const float4 fv = *(const float4*)&sm[rl * 128 + to * 4];
#pragma unroll
            for (int j = 0; j < 8; j++) {
                const float m = sm[MERGED_OFF + (bq * 8 + j) * PAD + r];
                acc2[j][0] = fmaf(m, fv.x, acc2[j][0]);
                acc2[j][1] = fmaf(m, fv.y, acc2[j][1]);
                acc2[j][2] = fmaf(m, fv.z, acc2[j][2]);
                acc2[j][3] = fmaf(m, fv.w, acc2[j][3]);
            }
        }
        __syncthreads();
    }

    // residual (mean over c of x) + store
#pragma unroll
    for (int j = 0; j < 8; j++) {
        const int b = bq * 8 + j;
        const int xb = ((b * N_ + n) * C_) * D_ + to * 4;
        const float4 r0 = *(const float4*)&x[xb + 0 * D_];
        const float4 r1 = *(const float4*)&x[xb + 1 * D_];
        const float4 r2 = *(const float4*)&x[xb + 2 * D_];
        const float4 r3 = *(const float4*)&x[xb + 3 * D_];
        float4 o;
        o.x = acc2[j][0] + 0.25f * (r0.x + r1.x + r2.x + r3.x);
        o.y = acc2[j][1] + 0.25f * (r0.y + r1.y + r2.y + r3.y);
        o.z = acc2[j][2] + 0.25f * (r0.z + r1.z + r2.z + r3.z);
        o.w = acc2[j][3] + 0.25f * (r0.w + r1.w + r2.w + r3.w);
        *(float4*)&out[(b * N_ + n) * O_ + to * 4] = o;
    }
}

extern "C" void kernel_launch(void* const* d_in, const int* in_sizes, int n_in,
                              void* d_out, int out_size)
{
    const float* x       = (const float*)d_in[0];
    const float* factors = (const float*)d_in[1];
    const float* fo      = (const float*)d_in[2];
    const float* gain    = (const float*)d_in[3];
    float* out = (float*)d_out;

    cudaFuncSetAttribute(cpquad_kernel,
                         cudaFuncAttributeMaxDynamicSharedMemorySize, SMEM_BYTES);
    cpquad_kernel<<<N_, 256, SMEM_BYTES>>>(x, factors, fo, gain, out);
}

// round 4
// speedup vs baseline: 1.5385x; 1.5224x over previous
#include <cuda_runtime.h>
#include <cuda_bf16.h>
#include <stdint.h>

// CPQuadRankLayer via mma.sync bf16 3-term split. B=64, N=1024, C=4, R=64, D=O=128.
//   P_c[b][r] = sum_i x[b,n,c,i] f[c,n,r,i]
//   p = P / rms_r(P); merged = prod_c p * gain; out = merged @ fo + 0.25*sum_c x

#define NN 1024

// smem byte offsets (projection phase)
#define XH_OFF   0        // 64 rows x 272B (128 bf16 + pad)
#define XL_OFF   17408
#define FH_OFF   34816
#define FL_OFF   52224
#define RES_OFF  69632    // 64x128 f32 = 32768
#define SS_OFF   102400   // ss[2][4][64] f32 = 2048
#define RINV_OFF 104448   // 64 f32
#define SMEM_BYTES 104704
// epilogue overlay (over X/F region)
#define MH_OFF   0        // merged hi: 64 rows x 144B (64 bf16 + pad)
#define ML_OFF   9216
#define FOH_OFF  18432    // fo^T hi: 128 rows x 144B (64 bf16 + pad)
#define FOL_OFF  36864

__device__ __forceinline__ void split2(float a, float b, uint32_t& hi, uint32_t& lo) {
    __nv_bfloat16 ah = __float2bfloat16(a), bh = __float2bfloat16(b);
    hi = ((uint32_t)__bfloat16_as_ushort(bh) << 16) | (uint32_t)__bfloat16_as_ushort(ah);
    __nv_bfloat16 al = __float2bfloat16(a - __bfloat162float(ah));
    __nv_bfloat16 bl = __float2bfloat16(b - __bfloat162float(bh));
    lo = ((uint32_t)__bfloat16_as_ushort(bl) << 16) | (uint32_t)__bfloat16_as_ushort(al);
}

__device__ __forceinline__ void mma_bf16(float* c, const uint32_t* a, const uint32_t* b) {
    asm volatile(
        "mma.sync.aligned.m16n8k16.row.col.f32.bf16.bf16.f32 "
        "{%0,%1,%2,%3}, {%4,%5,%6,%7}, {%8,%9}, {%0,%1,%2,%3};"
        : "+f"(c[0]), "+f"(c[1]), "+f"(c[2]), "+f"(c[3])
        : "r"(a[0]), "r"(a[1]), "r"(a[2]), "r"(a[3]), "r"(b[0]), "r"(b[1]));
}

__global__ __launch_bounds__(256, 1)
void cpquad_mma(const float* __restrict__ x, const float* __restrict__ f,
                const float* __restrict__ fo, const float* __restrict__ gain,
                float* __restrict__ out)
{
    extern __shared__ char sm[];
    const int n = blockIdx.x;
    const int t = threadIdx.x;
    const int lane = t & 31, wid = t >> 5;
    const int g = lane >> 2, tg = lane & 3;
    const int wb = wid >> 1, ws = wid & 1;   // wb: b-tile (16 rows); ws: r-half / o-half
    const int bb = wb * 16;
    const float gn = __ldg(&gain[n]);

    float4 xr[8], fr[8], resacc[8];
    float acc[4][4][4];
#pragma unroll
    for (int c = 0; c < 4; ++c)
#pragma unroll
        for (int nt = 0; nt < 4; ++nt)
#pragma unroll
            for (int u = 0; u < 4; ++u) acc[c][nt][u] = 0.0f;

    // prologue LDG for c=0: thread handles rows {wid+8j}, float4 col = lane
#pragma unroll
    for (int j = 0; j < 8; ++j) {
        const int row = j * 8 + wid;
        xr[j] = *(const float4*)(x + (((size_t)row * NN + n) * 4 + 0) * 128 + lane * 4);
        fr[j] = *(const float4*)(f + (((size_t)0 * NN + n) * 64 + row) * 128 + lane * 4);
    }

#pragma unroll
    for (int c = 0; c < 4; ++c) {
        // STS hi/lo split + residual accumulation
#pragma unroll
        for (int j = 0; j < 8; ++j) {
            const int row = j * 8 + wid;
            uint2 hi, lo;
            split2(xr[j].x, xr[j].y, hi.x, lo.x);
            split2(xr[j].z, xr[j].w, hi.y, lo.y);
            *(uint2*)(sm + XH_OFF + row * 272 + lane * 8) = hi;
            *(uint2*)(sm + XL_OFF + row * 272 + lane * 8) = lo;
            split2(fr[j].x, fr[j].y, hi.x, lo.x);
            split2(fr[j].z, fr[j].w, hi.y, lo.y);
            *(uint2*)(sm + FH_OFF + row * 272 + lane * 8) = hi;
            *(uint2*)(sm + FL_OFF + row * 272 + lane * 8) = lo;
            if (c == 0) resacc[j] = xr[j];
            else {
                resacc[j].x += xr[j].x; resacc[j].y += xr[j].y;
                resacc[j].z += xr[j].z; resacc[j].w += xr[j].w;
            }
        }
        __syncthreads();

        // prefetch next c (latency hides under mma block)
        if (c < 3) {
#pragma unroll
            for (int j = 0; j < 8; ++j) {
                const int row = j * 8 + wid;
                xr[j] = *(const float4*)(x + (((size_t)row * NN + n) * 4 + (c + 1)) * 128 + lane * 4);
                fr[j] = *(const float4*)(f + (((size_t)(c + 1) * NN + n) * 64 + row) * 128 + lane * 4);
            }
        }

        // projection MMAs: P_c tile 16b x 32r, K=128 (8 k16-steps), 3 split terms
#pragma unroll
        for (int kk = 0; kk < 8; ++kk) {
            uint32_t ah[4], al[4];
            const uint32_t ab = (uint32_t)((bb + g) * 272 + kk * 32 + tg * 4);
            ah[0] = *(const uint32_t*)(sm + XH_OFF + ab);
            ah[1] = *(const uint32_t*)(sm + XH_OFF + ab + 2176);
            ah[2] = *(const uint32_t*)(sm + XH_OFF + ab + 16);
            ah[3] = *(const uint32_t*)(sm + XH_OFF + ab + 2192);
            al[0] = *(const uint32_t*)(sm + XL_OFF + ab);
            al[1] = *(const uint32_t*)(sm + XL_OFF + ab + 2176);
            al[2] = *(const uint32_t*)(sm + XL_OFF + ab + 16);
            al[3] = *(const uint32_t*)(sm + XL_OFF + ab + 2192);
#pragma unroll
            for (int nt = 0; nt < 4; ++nt) {
                uint32_t bh[2], bl[2];
                const uint32_t bby = (uint32_t)((ws * 32 + nt * 8 + g) * 272 + kk * 32 + tg * 4);
                bh[0] = *(const uint32_t*)(sm + FH_OFF + bby);
                bh[1] = *(const uint32_t*)(sm + FH_OFF + bby + 16);
                bl[0] = *(const uint32_t*)(sm + FL_OFF + bby);
                bl[1] = *(const uint32_t*)(sm + FL_OFF + bby + 16);
                mma_bf16(acc[c][nt], ah, bh);
                mma_bf16(acc[c][nt], ah, bl);
                mma_bf16(acc[c][nt], al, bh);
            }
        }
        __syncthreads();
    }

    // ---- RMS partials: lane rows g, g+8; reduce over the 4 tg lanes ----
    float ssp[4][2];
#pragma unroll
    for (int c = 0; c < 4; ++c) {
        float s0 = 0.f, s1 = 0.f;
#pragma unroll
        for (int nt = 0; nt < 4; ++nt) {
            s0 = fmaf(acc[c][nt][0], acc[c][nt][0], s0);
            s0 = fmaf(acc[c][nt][1], acc[c][nt][1], s0);
            s1 = fmaf(acc[c][nt][2], acc[c][nt][2], s1);
            s1 = fmaf(acc[c][nt][3], acc[c][nt][3], s1);
        }
        s0 += __shfl_xor_sync(0xffffffffu, s0, 1);
        s0 += __shfl_xor_sync(0xffffffffu, s0, 2);
        s1 += __shfl_xor_sync(0xffffffffu, s1, 1);
        s1 += __shfl_xor_sync(0xffffffffu, s1, 2);
        ssp[c][0] = s0; ssp[c][1] = s1;
    }
    if (tg == 0) {
#pragma unroll
        for (int c = 0; c < 4; ++c) {
            *(float*)(sm + SS_OFF + (((ws * 4 + c) * 64) + bb + g) * 4)     = ssp[c][0];
            *(float*)(sm + SS_OFF + (((ws * 4 + c) * 64) + bb + g + 8) * 4) = ssp[c][1];
        }
    }
    // residual to smem
#pragma unroll
    for (int j = 0; j < 8; ++j)
        *(float4*)(sm + RES_OFF + (j * 8 + wid) * 512 + lane * 16) = resacc[j];
    __syncthreads();

    // rinv-product per b (first 64 threads) + fo^T staging (all threads, overlaps)
    if (t < 64) {
        float prod = gn;
#pragma unroll
        for (int c = 0; c < 4; ++c) {
            float s = *(const float*)(sm + SS_OFF + ((0 * 4 + c) * 64 + t) * 4)
                    + *(const float*)(sm + SS_OFF + ((1 * 4 + c) * 64 + t) * 4);
            prod *= rsqrtf(s * 0.015625f + 1e-6f);
        }
        *(float*)(sm + RINV_OFF + t * 4) = prod;
    }
    {
        const int o = t >> 1, rh = (t & 1) * 32;
        const float* fob = fo + (size_t)n * 8192 + o;
#pragma unroll
        for (int u = 0; u < 8; ++u) {
            const int r0 = rh + u * 4;
            float v0 = fob[(r0 + 0) * 128], v1 = fob[(r0 + 1) * 128];
            float v2 = fob[(r0 + 2) * 128], v3 = fob[(r0 + 3) * 128];
            uint2 hi, lo;
            split2(v0, v1, hi.x, lo.x);
            split2(v2, v3, hi.y, lo.y);
            *(uint2*)(sm + FOH_OFF + o * 144 + r0 * 2) = hi;
            *(uint2*)(sm + FOL_OFF + o * 144 + r0 * 2) = lo;
        }
    }
    __syncthreads();

    // merged = prod_c P * rinvprod  -> bf16 hi/lo tile [b][r]
    {
        const float r0v = *(const float*)(sm + RINV_OFF + (bb + g) * 4);
        const float r1v = *(const float*)(sm + RINV_OFF + (bb + g + 8) * 4);
#pragma unroll
        for (int nt = 0; nt < 4; ++nt) {
            const int rc = ws * 32 + nt * 8 + tg * 2;
            float m0 = acc[0][nt][0] * acc[1][nt][0] * acc[2][nt][0] * acc[3][nt][0] * r0v;
            float m1 = acc[0][nt][1] * acc[1][nt][1] * acc[2][nt][1] * acc[3][nt][1] * r0v;
            float m2 = acc[0][nt][2] * acc[1][nt][2] * acc[2][nt][2] * acc[3][nt][2] * r1v;
            float m3 = acc[0][nt][3] * acc[1][nt][3] * acc[2][nt][3] * acc[3][nt][3] * r1v;
            uint32_t h01, l01, h23, l23;
            split2(m0, m1, h01, l01);
            split2(m2, m3, h23, l23);
            *(uint32_t*)(sm + MH_OFF + (bb + g) * 144 + rc * 2)     = h01;
            *(uint32_t*)(sm + ML_OFF + (bb + g) * 144 + rc * 2)     = l01;
            *(uint32_t*)(sm + MH_OFF + (bb + g + 8) * 144 + rc * 2) = h23;
            *(uint32_t*)(sm + ML_OFF + (bb + g + 8) * 144 + rc * 2) = l23;
        }
    }
    __syncthreads();

    // output GEMM: warp = (wb, o-half ws): 16b x 64o, K=64 (4 k16-steps), 3 terms
    float acc2[8][4];
#pragma unroll
    for (int nt = 0; nt < 8; ++nt)
#pragma unroll
        for (int u = 0; u < 4; ++u) acc2[nt][u] = 0.0f;

    const int obase = ws * 64;
#pragma unroll
    for (int kk = 0; kk < 4; ++kk) {
        uint32_t ah[4], al[4];
        const uint32_t ab = (uint32_t)((bb + g) * 144 + kk * 32 + tg * 4);
        ah[0] = *(const uint32_t*)(sm + MH_OFF + ab);
        ah[1] = *(const uint32_t*)(sm + MH_OFF + ab + 1152);
        ah[2] = *(const uint32_t*)(sm + MH_OFF + ab + 16);
        ah[3] = *(const uint32_t*)(sm + MH_OFF + ab + 1168);
        al[0] = *(const uint32_t*)(sm + ML_OFF + ab);
        al[1] = *(const uint32_t*)(sm + ML_OFF + ab + 1152);
        al[2] = *(const uint32_t*)(sm + ML_OFF + ab + 16);
        al[3] = *(const uint32_t*)(sm + ML_OFF + ab + 1168);
#pragma unroll
        for (int nt = 0; nt < 8; ++nt) {
            uint32_t bh[2], bl[2];
            const uint32_t bby = (uint32_t)((obase + nt * 8 + g) * 144 + kk * 32 + tg * 4);
            bh[0] = *(const uint32_t*)(sm + FOH_OFF + bby);
            bh[1] = *(const uint32_t*)(sm + FOH_OFF + bby + 16);
            bl[0] = *(const uint32_t*)(sm + FOL_OFF + bby);
            bl[1] = *(const uint32_t*)(sm + FOL_OFF + bby + 16);
            mma_bf16(acc2[nt], ah, bh);
            mma_bf16(acc2[nt], ah, bl);
            mma_bf16(acc2[nt], al, bh);
        }
    }

    // store with residual mean
#pragma unroll
    for (int nt = 0; nt < 8; ++nt) {
        const int oc = obase + nt * 8 + tg * 2;
        const int b0 = bb + g, b1 = bb + g + 8;
        const float2 r0 = *(const float2*)(sm + RES_OFF + (b0 * 128 + oc) * 4);
        const float2 r1 = *(const float2*)(sm + RES_OFF + (b1 * 128 + oc) * 4);
        float2 o0, o1;
        o0.x = acc2[nt][0] + 0.25f * r0.x;
        o0.y = acc2[nt][1] + 0.25f * r0.y;
        o1.x = acc2[nt][2] + 0.25f * r1.x;
        o1.y = acc2[nt][3] + 0.25f * r1.y;
        *(float2*)(out + ((size_t)b0 * NN + n) * 128 + oc) = o0;
        *(float2*)(out + ((size_t)b1 * NN + n) * 128 + oc) = o1;
    }
}

extern "C" void kernel_launch(void* const* d_in, const int* in_sizes, int n_in,
                              void* d_out, int out_size)
{
    const float* x       = (const float*)d_in[0];
    const float* factors = (const float*)d_in[1];
    const float* fo      = (const float*)d_in[2];
    const float* gain    = (const float*)d_in[3];
    float* out = (float*)d_out;

    cudaFuncSetAttribute(cpquad_mma, cudaFuncAttributeMaxDynamicSharedMemorySize, SMEM_BYTES);
    cpquad_mma<<<NN, 256, SMEM_BYTES>>>(x, factors, fo, gain, out);
}